// round 15
// baseline (speedup 1.0000x reference)
#include <cuda_runtime.h>
#include <cuda_bf16.h>
#include <math.h>
#include <stdint.h>

// Fixed problem shape: B=64, D=3072, N=50000.
#define BFIX 64
#define DFIX 3072
#define RCAP 50048

// ---------------- scratch (__device__ globals: allocation-free) -------------
__device__ float g_logits[(size_t)BFIX * 50048];
__device__ float g_px[BFIX * 4];
__device__ float g_mc[BFIX];              // cheap per-b max logit
__device__ float g_m[BFIX];               // exact max (refined)
__device__ float g_is[BFIX];              // exact 1/S
__device__ __nv_bfloat16 g_xhi[BFIX * DFIX];
__device__ float g_pm[BFIX * 512];        // per-(b,tile) cheap max
__device__ int g_wl[BFIX * 512];          // candidate tile worklist
__device__ int g_wcnt;
__device__ int g_rn[(size_t)BFIX * RCAP]; // refined row indices per b
__device__ int g_rcnt[BFIX];

// ---------------- helpers ----------------------------------------------------
__device__ __forceinline__ uint32_t smem_u32(const void* p) {
    uint32_t a;
    asm("{ .reg .u64 t; cvta.to.shared.u64 t, %1; cvt.u32.u64 %0, t; }"
        : "=r"(a) : "l"(p));
    return a;
}
#define SMEM_SWZ(o) ((o) ^ (((o) >> 3) & 0x70))

#define LDSM_X4(r, addr) \
    asm volatile("ldmatrix.sync.aligned.m8n8.x4.shared.b16 {%0,%1,%2,%3}, [%4];" \
        : "=r"((r)[0]), "=r"((r)[1]), "=r"((r)[2]), "=r"((r)[3]) : "r"(addr))

#define MMA16816(d, a, b0, b1) \
    asm volatile("mma.sync.aligned.m16n8k16.row.col.f32.bf16.bf16.f32 " \
        "{%0,%1,%2,%3}, {%4,%5,%6,%7}, {%8,%9}, {%0,%1,%2,%3};" \
        : "+f"((d)[0]), "+f"((d)[1]), "+f"((d)[2]), "+f"((d)[3]) \
        : "r"((a)[0]), "r"((a)[1]), "r"((a)[2]), "r"((a)[3]), "r"(b0), "r"(b1))

#define CVT2BF(d, x, y) \
    asm("cvt.rn.bf16x2.f32 %0, %1, %2;" : "=r"(d) : "f"(y), "f"(x))

#define MBARRIER_INIT(addr, cnt) \
    asm volatile("mbarrier.init.shared.b64 [%0], %1;" :: "r"((uint32_t)(addr)), "r"((uint32_t)(cnt)) : "memory")
#define MBARRIER_ARRIVE(addr) \
    asm volatile("mbarrier.arrive.shared.b64 _, [%0];" :: "r"((uint32_t)(addr)) : "memory")
#define MBARRIER_WAIT_PARITY(mbar_smem_addr, phase_parity) do { \
    uint32_t _mbar = (uint32_t)(mbar_smem_addr); \
    uint32_t _parity = (uint32_t)(phase_parity); \
    uint32_t _done; \
    asm volatile("{\n\t.reg .pred p;\n\t" \
        "mbarrier.try_wait.parity.shared.b64 p, [%1], %2;\n\t" \
        "selp.b32 %0, 1, 0, p;\n\t}" : "=r"(_done) : "r"(_mbar), "r"(_parity) : "memory"); \
    if (!_done) { \
        asm volatile("{\n\t.reg .pred P1;\n\t" \
            "WAIT_LOOP_%=:\n\t" \
            "mbarrier.try_wait.parity.shared.b64 P1, [%0], %1;\n\t" \
            "@P1 bra.uni WAIT_DONE_%=;\n\t" \
            "bra.uni WAIT_LOOP_%=;\n\t" \
            "WAIT_DONE_%=:\n\t}" :: "r"(_mbar), "r"(_parity) : "memory"); \
    } \
} while (0)

// ---------------------------------------------------------------------------
// K0: grid (B, 4). bf16 hi split of x + out-zero + partial ||x||^2 + counters.
// ---------------------------------------------------------------------------
__global__ void k_prep(const float* __restrict__ x,
                       float* __restrict__ out, int D) {
    int b = blockIdx.x, c = blockIdx.y;
    if (threadIdx.x == 0 && c == 0) {
        g_rcnt[b] = 0;
        if (b == 0) g_wcnt = 0;
    }
    int q = D / 4;
    int d0 = c * q;
    const float* xr = x + (size_t)b * D;
    float s = 0.f;
    for (int d = d0 + threadIdx.x; d < d0 + q; d += blockDim.x) {
        float v = xr[d];
        s += v * v;
        g_xhi[(size_t)b * D + d] = __float2bfloat16(v);
        out[(size_t)b * D + d] = 0.f;
    }
    __shared__ float red[256];
    red[threadIdx.x] = s;
    __syncthreads();
    for (int o = 128; o > 0; o >>= 1) {
        if (threadIdx.x < o) red[threadIdx.x] += red[threadIdx.x + o];
        __syncthreads();
    }
    if (threadIdx.x == 0) g_px[b * 4 + c] = red[0];
}

// ---------------------------------------------------------------------------
// K1: warp-specialized 1-TERM bf16 HMMA GEMM (hi*hi only) -> CHEAP logits
// (selection only) + per-tile max. mbarriers, 4-stage pipeline.
// ---------------------------------------------------------------------------
#define NT 128
#define KC 64
#define STAGES 4
#define A_HI_SZ 8192
#define BUF_SZ  24576           // A_hi (8KB) + B_hi (16KB)
#define SOFF_RED  0
#define SOFF_Y2   1024
#define SOFF_BAR  1536
#define SMEM_PRE  2048
#define SMEM_TOTAL (SMEM_PRE + 1024 + STAGES * BUF_SZ)

__global__ void __launch_bounds__(512, 1)
k_gemm(const float* __restrict__ Y, const float* __restrict__ sigma,
       int N, int D) {
    extern __shared__ char smem[];
    uint32_t sb = smem_u32(smem);
    const int t = threadIdx.x, w = t >> 5, lane = t & 31;
    const int n0 = blockIdx.x * NT;
    const int NC = D / KC;   // 48

    uint32_t tile0 = (sb + SMEM_PRE + 1023) & ~1023u;
    char* sm_t = smem + (tile0 - sb);
    float* redp = (float*)(smem + SOFF_RED);
    float* y2s  = (float*)(smem + SOFF_Y2);

    if (t == 0) {
#pragma unroll
        for (int s = 0; s < STAGES; s++) {
            MBARRIER_INIT(sb + SOFF_BAR + s * 16, 256);
            MBARRIER_INIT(sb + SOFF_BAR + s * 16 + 8, 256);
        }
    }
    __syncthreads();

    float y2p = 0.f;
    float acc[2][4][4];
#pragma unroll
    for (int i = 0; i < 2; i++)
#pragma unroll
        for (int j = 0; j < 4; j++)
#pragma unroll
            for (int k = 0; k < 4; k++) acc[i][j][k] = 0.f;

    if (t < 256) {
        // ================= PRODUCER (warps 0-7) =================
        const int r  = t >> 1;
        const int ch = (t & 1) * 32;
        int gr = n0 + r; if (gr >= N) gr = N - 1;
        const float* yp = Y + (size_t)gr * D + ch;
        const int ar = t >> 2, ap = t & 3;
        const __nv_bfloat16* xhp = g_xhi + (size_t)ar * D + ap * 16;

        float4 yv[8];
        uint4 ahv[2];
#pragma unroll
        for (int j = 0; j < 8; j++) yv[j] = *(const float4*)(yp + j * 4);
        ahv[0] = *(const uint4*)(xhp); ahv[1] = *(const uint4*)(xhp + 8);

        int buf = 0, ph = 1;
#pragma unroll 1
        for (int ci = 0; ci < NC; ci++) {
            MBARRIER_WAIT_PARITY(sb + SOFF_BAR + buf * 16 + 8, ph);
            {
                char* base = sm_t + buf * BUF_SZ;
                char* bh = base + A_HI_SZ;
#pragma unroll
                for (int j = 0; j < 8; j += 2) {
                    float4 v0 = yv[j], v1 = yv[j + 1];
                    y2p = fmaf(v0.x, v0.x, y2p); y2p = fmaf(v0.y, v0.y, y2p);
                    y2p = fmaf(v0.z, v0.z, y2p); y2p = fmaf(v0.w, v0.w, y2p);
                    y2p = fmaf(v1.x, v1.x, y2p); y2p = fmaf(v1.y, v1.y, y2p);
                    y2p = fmaf(v1.z, v1.z, y2p); y2p = fmaf(v1.w, v1.w, y2p);
                    uint32_t h0, h1, h2, h3;
                    CVT2BF(h0, v0.x, v0.y);
                    CVT2BF(h1, v0.z, v0.w);
                    CVT2BF(h2, v1.x, v1.y);
                    CVT2BF(h3, v1.z, v1.w);
                    uint32_t bo = SMEM_SWZ((uint32_t)(r * 128 + (ch + j * 4) * 2));
                    *(uint4*)(bh + bo) = make_uint4(h0, h1, h2, h3);
                }
#pragma unroll
                for (int u = 0; u < 2; u++) {
                    uint32_t bo = SMEM_SWZ((uint32_t)(ar * 128 + ap * 32 + u * 16));
                    *(uint4*)(base + bo) = ahv[u];
                }
            }
            MBARRIER_ARRIVE(sb + SOFF_BAR + buf * 16);
            if (++buf == STAGES) { buf = 0; ph ^= 1; }
            if (ci + 1 < NC) {
                int k0 = (ci + 1) * KC;
#pragma unroll
                for (int j = 0; j < 8; j++) yv[j] = *(const float4*)(yp + k0 + j * 4);
                ahv[0] = *(const uint4*)(xhp + k0); ahv[1] = *(const uint4*)(xhp + k0 + 8);
            }
        }
    } else {
        // ================= CONSUMER (warps 8-15) =================
        const int cw = w - 8;
        const int wm = cw & 1;
        const int wn = cw >> 1;
        const int rowA = wm * 32 + (lane & 15);
        const int rowB = wn * 32 + (lane & 15);
        const uint32_t kbl = (uint32_t)(lane >> 4) * 16;

        int buf = 0, ph = 0;
#pragma unroll 1
        for (int ci = 0; ci < NC; ci++) {
            MBARRIER_WAIT_PARITY(sb + SOFF_BAR + buf * 16, ph);
            uint32_t base = tile0 + buf * BUF_SZ;
#pragma unroll
            for (int ks = 0; ks < 4; ks++) {
                uint32_t kb = (uint32_t)ks * 32 + kbl;
                uint32_t offA0 = SMEM_SWZ((uint32_t)(rowA * 128) + kb);
                uint32_t offA1 = SMEM_SWZ((uint32_t)((rowA + 16) * 128) + kb);
                uint32_t offB0 = SMEM_SWZ((uint32_t)(rowB * 128) + kb);
                uint32_t offB1 = SMEM_SWZ((uint32_t)((rowB + 16) * 128) + kb);
                uint32_t ah0[4], ah1[4], bh0[4], bh1[4];
                LDSM_X4(ah0, base + offA0);
                LDSM_X4(ah1, base + offA1);
                LDSM_X4(bh0, base + A_HI_SZ + offB0);
                LDSM_X4(bh1, base + A_HI_SZ + offB1);
#pragma unroll
                for (int nt = 0; nt < 4; nt++) {
                    uint32_t* BH = (nt < 2) ? bh0 : bh1;
                    int p = nt & 1;
                    MMA16816(acc[0][nt], ah0, BH[p], BH[2 + p]);
                    MMA16816(acc[1][nt], ah1, BH[p], BH[2 + p]);
                }
            }
            MBARRIER_ARRIVE(sb + SOFF_BAR + buf * 16 + 8);
            if (++buf == STAGES) { buf = 0; ph ^= 1; }
        }
    }

    // ================= EPILOGUE =================
    if (t < 256) redp[t] = y2p;
    __syncthreads();
    float* lt = (float*)sm_t;   // stages 0-1 (49KB) free; need 32KB
    if (w >= 8) {
        const int cw = w - 8;
        const int wm = cw & 1;
        const int wn = cw >> 1;
#pragma unroll
        for (int mt = 0; mt < 2; mt++) {
#pragma unroll
            for (int nt = 0; nt < 4; nt++) {
                int mrow = wm * 32 + mt * 16 + (lane >> 2);
                int col  = wn * 32 + nt * 8 + (lane & 3) * 2;
                lt[mrow * 128 + col]           = acc[mt][nt][0];
                lt[mrow * 128 + col + 1]       = acc[mt][nt][1];
                lt[(mrow + 8) * 128 + col]     = acc[mt][nt][2];
                lt[(mrow + 8) * 128 + col + 1] = acc[mt][nt][3];
            }
        }
    }
    if (t < 128) y2s[t] = redp[2 * t] + redp[2 * t + 1];
    __syncthreads();

    const int GB = gridDim.x;
#pragma unroll
    for (int it = 0; it < 4; it++) {
        int b = it * 16 + w;
        int nn = lane * 4;
        int n = n0 + nn;
        float x2b = (g_px[b * 4 + 0] + g_px[b * 4 + 1])
                  + (g_px[b * 4 + 2] + g_px[b * 4 + 3]);
        float sg = sigma[b];
        float iv = 1.0f / (sg * sg);
        float4 o = make_float4(0.f, 0.f, 0.f, 0.f);
        bool valid = (n < N);
        if (valid) {
            float4 dv = *(float4*)(lt + b * 128 + nn);
            o.x = -0.5f * fmaxf(x2b + y2s[nn]     - 2.0f * dv.x, 0.0f) * iv;
            o.y = -0.5f * fmaxf(x2b + y2s[nn + 1] - 2.0f * dv.y, 0.0f) * iv;
            o.z = -0.5f * fmaxf(x2b + y2s[nn + 2] - 2.0f * dv.z, 0.0f) * iv;
            o.w = -0.5f * fmaxf(x2b + y2s[nn + 3] - 2.0f * dv.w, 0.0f) * iv;
            *(float4*)(g_logits + (size_t)b * N + n) = o;
        }
        float mx = valid ? fmaxf(fmaxf(o.x, o.y), fmaxf(o.z, o.w)) : -3.4e38f;
#pragma unroll
        for (int q = 16; q > 0; q >>= 1)
            mx = fmaxf(mx, __shfl_xor_sync(0xffffffff, mx, q));
        if (lane == 0) g_pm[(size_t)b * GB + blockIdx.x] = mx;
    }
}

// ---------------------------------------------------------------------------
// K2: per-b cheap max + candidate tile worklist (margin-expanded threshold).
// ---------------------------------------------------------------------------
__global__ void k_sel(const float* __restrict__ sigma, int GB) {
    int b = blockIdx.x, t = threadIdx.x;
    __shared__ float red[256];
    const float* pm = g_pm + (size_t)b * GB;
    float m = -3.4e38f;
    for (int i = t; i < GB; i += 256) m = fmaxf(m, pm[i]);
    red[t] = m;
    __syncthreads();
    for (int o = 128; o > 0; o >>= 1) {
        if (t < o) red[t] = fmaxf(red[t], red[t + o]);
        __syncthreads();
    }
    float M = red[0];
    if (t == 0) g_mc[b] = M;
    float sg = sigma[b];
    float inv = 1.0f / (sg * sg);
    float margin = 2.5f * inv + 1.0f;
    float thr = M - 27.631f - 2.0f * margin;
    for (int i = t; i < GB; i += 256) {
        if (pm[i] >= thr) {
            int p = atomicAdd(&g_wcnt, 1);
            g_wl[p] = (b << 9) | i;
        }
    }
}

// ---------------------------------------------------------------------------
// K3: refine candidate rows with exact fp32 dot (one warp per row); write
// refined logits in place and collect per-b refined row lists.
// ---------------------------------------------------------------------------
#define RGRID 512

__global__ void __launch_bounds__(256)
k_refine(const float* __restrict__ x, const float* __restrict__ Y,
         const float* __restrict__ sigma, int N, int D) {
    int t = threadIdx.x, lane = t & 31, w = t >> 5;
    __shared__ int q[128];
    __shared__ int qc;

    int total = g_wcnt;
#pragma unroll 1
    for (int idx = blockIdx.x; idx < total; idx += RGRID) {
        int e  = g_wl[idx];
        int b  = e >> 9;
        int ti = e & 511;
        float sg = sigma[b];
        float inv = 1.0f / (sg * sg);
        float margin = 2.5f * inv + 1.0f;
        float thr = g_mc[b] - 27.631f - 2.0f * margin;
        float x2b = (g_px[b * 4 + 0] + g_px[b * 4 + 1])
                  + (g_px[b * 4 + 2] + g_px[b * 4 + 3]);

        if (t == 0) qc = 0;
        __syncthreads();
        if (t < 128) {
            int n = ti * 128 + t;
            if (n < N && g_logits[(size_t)b * N + n] >= thr) {
                int p = atomicAdd(&qc, 1);
                q[p] = n;
            }
        }
        __syncthreads();
        int c = qc;
        const float* xr = x + (size_t)b * D;
        for (int i = w; i < c; i += 8) {
            int n = q[i];
            const float* yr = Y + (size_t)n * D;
            float dot = 0.f, y2 = 0.f;
#pragma unroll 4
            for (int k = lane; k < D; k += 32) {
                float yv = yr[k], xv = xr[k];
                dot = fmaf(xv, yv, dot);
                y2  = fmaf(yv, yv, y2);
            }
#pragma unroll
            for (int o = 16; o > 0; o >>= 1) {
                dot += __shfl_xor_sync(0xffffffff, dot, o);
                y2  += __shfl_xor_sync(0xffffffff, y2, o);
            }
            if (lane == 0) {
                float d2 = fmaxf(x2b + y2 - 2.0f * dot, 0.0f);
                g_logits[(size_t)b * N + n] = -0.5f * d2 * inv;
                int p = atomicAdd(&g_rcnt[b], 1);
                g_rn[(size_t)b * RCAP + p] = n;
            }
        }
        __syncthreads();
    }
}

// ---------------------------------------------------------------------------
// K4: exact softmax stats over refined rows.
// ---------------------------------------------------------------------------
__global__ void k_final(int N) {
    int b = blockIdx.x, t = threadIdx.x;
    __shared__ float red[256];
    int rc = g_rcnt[b];
    const int* rn = g_rn + (size_t)b * RCAP;
    const float* row = g_logits + (size_t)b * N;
    float m = -3.4e38f;
    for (int i = t; i < rc; i += 256) m = fmaxf(m, row[rn[i]]);
    red[t] = m;
    __syncthreads();
    for (int o = 128; o > 0; o >>= 1) {
        if (t < o) red[t] = fmaxf(red[t], red[t + o]);
        __syncthreads();
    }
    float M = red[0];
    __syncthreads();
    float s = 0.f;
    for (int i = t; i < rc; i += 256) s += expf(row[rn[i]] - M);
    red[t] = s;
    __syncthreads();
    for (int o = 128; o > 0; o >>= 1) {
        if (t < o) red[t] += red[t + o];
        __syncthreads();
    }
    if (t == 0) { g_m[b] = M; g_is[b] = 1.0f / red[0]; }
}

// ---------------------------------------------------------------------------
// K5: weighted gather over refined rows. grid (B, 8).
// ---------------------------------------------------------------------------
#define DREG (DFIX / 256)

__global__ void __launch_bounds__(256)
k_out(const float* __restrict__ Y, float* __restrict__ out, int N, int D) {
    int b = blockIdx.x, s = blockIdx.y, t = threadIdx.x;
    int rc = g_rcnt[b];
    float M  = g_m[b];
    float IS = g_is[b];
    const int* rn = g_rn + (size_t)b * RCAP;
    const float* row = g_logits + (size_t)b * N;

    float racc[DREG];
#pragma unroll
    for (int i = 0; i < DREG; i++) racc[i] = 0.f;
    bool used = false;

    for (int i = s; i < rc; i += 8) {
        int n = rn[i];
        float wv = expf(row[n] - M) * IS;
        if (wv > 1e-12f) {
            used = true;
            const float* yr = Y + (size_t)n * D + t;
#pragma unroll
            for (int j = 0; j < DREG; j++)
                racc[j] = fmaf(wv, yr[j * 256], racc[j]);
        }
    }
    if (used) {
#pragma unroll
        for (int j = 0; j < DREG; j++)
            atomicAdd(&out[(size_t)b * D + t + j * 256], racc[j]);
    }
}

// ---------------------------------------------------------------------------
extern "C" void kernel_launch(void* const* d_in, const int* in_sizes, int n_in,
                              void* d_out, int out_size) {
    const float* x     = (const float*)d_in[0];
    const float* sigma = (const float*)d_in[1];
    const float* Y     = (const float*)d_in[2];
    float* out = (float*)d_out;

    int B = in_sizes[1];             // 64
    int D = in_sizes[0] / B;         // 3072
    int N = in_sizes[2] / D;         // 50000
    int GB = (N + NT - 1) / NT;      // 391

    cudaFuncSetAttribute(k_gemm, cudaFuncAttributeMaxDynamicSharedMemorySize, SMEM_TOTAL);

    dim3 gp(B, 4);
    k_prep<<<gp, 256>>>(x, out, D);
    k_gemm<<<GB, 512, SMEM_TOTAL>>>(Y, sigma, N, D);
    k_sel<<<B, 256>>>(sigma, GB);
    k_refine<<<RGRID, 256>>>(x, Y, sigma, N, D);
    k_final<<<B, 256>>>(N);
    dim3 go(B, 8);
    k_out<<<go, 256>>>(Y, out, N, D);
}

// round 16
// speedup vs baseline: 1.6390x; 1.6390x over previous
#include <cuda_runtime.h>
#include <cuda_bf16.h>
#include <math.h>
#include <stdint.h>

// Fixed problem shape: B=64, D=3072, N=50000.
#define BFIX 64
#define DFIX 3072

// ---------------- scratch (__device__ globals: allocation-free) -------------
__device__ float g_logits[(size_t)BFIX * 50048];
__device__ float g_px[BFIX * 4];          // per-(b, quarter) partial ||x||^2
__device__ float g_m[BFIX];
__device__ float g_is[BFIX];
__device__ __nv_bfloat16 g_xhi[BFIX * DFIX];
__device__ __nv_bfloat16 g_xlo[BFIX * DFIX];
__device__ float g_pm[BFIX * 512];
__device__ float g_ps[BFIX * 512];
__device__ int g_wl[BFIX * 512];          // hot (b, tile) worklist
__device__ int g_wcnt;

// ---------------- helpers ----------------------------------------------------
__device__ __forceinline__ uint32_t smem_u32(const void* p) {
    uint32_t a;
    asm("{ .reg .u64 t; cvta.to.shared.u64 t, %1; cvt.u32.u64 %0, t; }"
        : "=r"(a) : "l"(p));
    return a;
}
#define SMEM_SWZ(o) ((o) ^ (((o) >> 3) & 0x70))

#define LDSM_X4(r, addr) \
    asm volatile("ldmatrix.sync.aligned.m8n8.x4.shared.b16 {%0,%1,%2,%3}, [%4];" \
        : "=r"((r)[0]), "=r"((r)[1]), "=r"((r)[2]), "=r"((r)[3]) : "r"(addr))

#define MMA16816(d, a, b0, b1) \
    asm volatile("mma.sync.aligned.m16n8k16.row.col.f32.bf16.bf16.f32 " \
        "{%0,%1,%2,%3}, {%4,%5,%6,%7}, {%8,%9}, {%0,%1,%2,%3};" \
        : "+f"((d)[0]), "+f"((d)[1]), "+f"((d)[2]), "+f"((d)[3]) \
        : "r"((a)[0]), "r"((a)[1]), "r"((a)[2]), "r"((a)[3]), "r"(b0), "r"(b1))

// d = { lo = bf16(x), hi = bf16(y) }
#define CVT2BF(d, x, y) \
    asm("cvt.rn.bf16x2.f32 %0, %1, %2;" : "=r"(d) : "f"(y), "f"(x))

#define MBARRIER_INIT(addr, cnt) \
    asm volatile("mbarrier.init.shared.b64 [%0], %1;" :: "r"((uint32_t)(addr)), "r"((uint32_t)(cnt)) : "memory")
#define MBARRIER_ARRIVE(addr) \
    asm volatile("mbarrier.arrive.shared.b64 _, [%0];" :: "r"((uint32_t)(addr)) : "memory")
#define MBARRIER_WAIT_PARITY(mbar_smem_addr, phase_parity) do { \
    uint32_t _mbar = (uint32_t)(mbar_smem_addr); \
    uint32_t _parity = (uint32_t)(phase_parity); \
    uint32_t _done; \
    asm volatile("{\n\t.reg .pred p;\n\t" \
        "mbarrier.try_wait.parity.shared.b64 p, [%1], %2;\n\t" \
        "selp.b32 %0, 1, 0, p;\n\t}" : "=r"(_done) : "r"(_mbar), "r"(_parity) : "memory"); \
    if (!_done) { \
        asm volatile("{\n\t.reg .pred P1;\n\t" \
            "WAIT_LOOP_%=:\n\t" \
            "mbarrier.try_wait.parity.shared.b64 P1, [%0], %1;\n\t" \
            "@P1 bra.uni WAIT_DONE_%=;\n\t" \
            "bra.uni WAIT_LOOP_%=;\n\t" \
            "WAIT_DONE_%=:\n\t}" :: "r"(_mbar), "r"(_parity) : "memory"); \
    } \
} while (0)

// ---------------------------------------------------------------------------
// K0: grid (B, 4). bf16 hi/lo split + out-zero + partial ||x||^2 per quarter.
// Block (0,0) also resets the worklist counter.
// ---------------------------------------------------------------------------
__global__ void k_prep(const float* __restrict__ x,
                       float* __restrict__ out, int D) {
    int b = blockIdx.x, c = blockIdx.y;
    if (b == 0 && c == 0 && threadIdx.x == 0) g_wcnt = 0;
    int q = D / 4;                       // 768
    int d0 = c * q;
    const float* xr = x + (size_t)b * D;
    float s = 0.f;
    for (int d = d0 + threadIdx.x; d < d0 + q; d += blockDim.x) {
        float v = xr[d];
        s += v * v;
        __nv_bfloat16 hi = __float2bfloat16(v);
        float lof = v - __bfloat162float(hi);
        g_xhi[(size_t)b * D + d] = hi;
        g_xlo[(size_t)b * D + d] = __float2bfloat16(lof);
        out[(size_t)b * D + d] = 0.f;
    }
    __shared__ float red[256];
    red[threadIdx.x] = s;
    __syncthreads();
    for (int o = 128; o > 0; o >>= 1) {
        if (threadIdx.x < o) red[threadIdx.x] += red[threadIdx.x + o];
        __syncthreads();
    }
    if (threadIdx.x == 0) g_px[b * 4 + c] = red[0];
}

// ---------------------------------------------------------------------------
// K1: warp-specialized HMMA bf16-split GEMM + fused logits/softmax partials.
// mbarriers, per-thread arrives, 3-stage pipeline. (Frozen mainloop.)
// ---------------------------------------------------------------------------
#define NT 128
#define KC 64
#define STAGES 3
#define TILE_A_LO 8192
#define TILE_B_HI 16384
#define TILE_B_LO 32768
#define BUF_SZ    49152
#define SOFF_RED  0
#define SOFF_Y2   1024
#define SOFF_BAR  1536          // STAGES x (full, empty) pairs, 16B stride
#define SMEM_PRE  2048
#define SMEM_TOTAL (SMEM_PRE + 1024 + STAGES * BUF_SZ)

__global__ void __launch_bounds__(512, 1)
k_gemm(const float* __restrict__ Y, const float* __restrict__ sigma,
       int N, int D) {
    extern __shared__ char smem[];
    uint32_t sb = smem_u32(smem);
    const int t = threadIdx.x, w = t >> 5, lane = t & 31;
    const int n0 = blockIdx.x * NT;
    const int NC = D / KC;   // 48

    uint32_t tile0 = (sb + SMEM_PRE + 1023) & ~1023u;
    char* sm_t = smem + (tile0 - sb);
    float* redp = (float*)(smem + SOFF_RED);
    float* y2s  = (float*)(smem + SOFF_Y2);

    if (t == 0) {
#pragma unroll
        for (int s = 0; s < STAGES; s++) {
            MBARRIER_INIT(sb + SOFF_BAR + s * 16, 256);       // full[s]
            MBARRIER_INIT(sb + SOFF_BAR + s * 16 + 8, 256);   // empty[s]
        }
    }
    __syncthreads();

    float y2p = 0.f;
    float acc[2][4][4];
#pragma unroll
    for (int i = 0; i < 2; i++)
#pragma unroll
        for (int j = 0; j < 4; j++)
#pragma unroll
            for (int k = 0; k < 4; k++) acc[i][j][k] = 0.f;

    if (t < 256) {
        // ================= PRODUCER (warps 0-7) =================
        const int r  = t >> 1;
        const int ch = (t & 1) * 32;
        int gr = n0 + r; if (gr >= N) gr = N - 1;
        const float* yp = Y + (size_t)gr * D + ch;
        const int ar = t >> 2, ap = t & 3;
        const __nv_bfloat16* xhp = g_xhi + (size_t)ar * D + ap * 16;
        const __nv_bfloat16* xlp = g_xlo + (size_t)ar * D + ap * 16;

        float4 yv[8];
        uint4 ahv[2], alv[2];
#pragma unroll
        for (int j = 0; j < 8; j++) yv[j] = *(const float4*)(yp + j * 4);
        ahv[0] = *(const uint4*)(xhp); ahv[1] = *(const uint4*)(xhp + 8);
        alv[0] = *(const uint4*)(xlp); alv[1] = *(const uint4*)(xlp + 8);

        int buf = 0, ph = 1;      // producer cursor
#pragma unroll 1
        for (int ci = 0; ci < NC; ci++) {
            MBARRIER_WAIT_PARITY(sb + SOFF_BAR + buf * 16 + 8, ph);  // empty[buf]
            {
                char* base = sm_t + buf * BUF_SZ;
                char* bh = base + TILE_B_HI;
                char* bl = base + TILE_B_LO;
#pragma unroll
                for (int j = 0; j < 8; j += 2) {
                    float4 v0 = yv[j], v1 = yv[j + 1];
                    y2p = fmaf(v0.x, v0.x, y2p); y2p = fmaf(v0.y, v0.y, y2p);
                    y2p = fmaf(v0.z, v0.z, y2p); y2p = fmaf(v0.w, v0.w, y2p);
                    y2p = fmaf(v1.x, v1.x, y2p); y2p = fmaf(v1.y, v1.y, y2p);
                    y2p = fmaf(v1.z, v1.z, y2p); y2p = fmaf(v1.w, v1.w, y2p);
                    uint32_t h0, h1, h2, h3, l0, l1, l2, l3;
                    CVT2BF(h0, v0.x, v0.y);
                    CVT2BF(h1, v0.z, v0.w);
                    CVT2BF(h2, v1.x, v1.y);
                    CVT2BF(h3, v1.z, v1.w);
                    CVT2BF(l0, v0.x - __uint_as_float(h0 << 16),
                               v0.y - __uint_as_float(h0 & 0xffff0000u));
                    CVT2BF(l1, v0.z - __uint_as_float(h1 << 16),
                               v0.w - __uint_as_float(h1 & 0xffff0000u));
                    CVT2BF(l2, v1.x - __uint_as_float(h2 << 16),
                               v1.y - __uint_as_float(h2 & 0xffff0000u));
                    CVT2BF(l3, v1.z - __uint_as_float(h3 << 16),
                               v1.w - __uint_as_float(h3 & 0xffff0000u));
                    uint32_t bo = SMEM_SWZ((uint32_t)(r * 128 + (ch + j * 4) * 2));
                    *(uint4*)(bh + bo) = make_uint4(h0, h1, h2, h3);
                    *(uint4*)(bl + bo) = make_uint4(l0, l1, l2, l3);
                }
                char* aH = base;
                char* aL = base + TILE_A_LO;
#pragma unroll
                for (int u = 0; u < 2; u++) {
                    uint32_t bo = SMEM_SWZ((uint32_t)(ar * 128 + ap * 32 + u * 16));
                    *(uint4*)(aH + bo) = ahv[u];
                    *(uint4*)(aL + bo) = alv[u];
                }
            }
            MBARRIER_ARRIVE(sb + SOFF_BAR + buf * 16);               // full[buf]
            if (++buf == STAGES) { buf = 0; ph ^= 1; }
            if (ci + 1 < NC) {
                int k0 = (ci + 1) * KC;
#pragma unroll
                for (int j = 0; j < 8; j++) yv[j] = *(const float4*)(yp + k0 + j * 4);
                ahv[0] = *(const uint4*)(xhp + k0); ahv[1] = *(const uint4*)(xhp + k0 + 8);
                alv[0] = *(const uint4*)(xlp + k0); alv[1] = *(const uint4*)(xlp + k0 + 8);
            }
        }
    } else {
        // ================= CONSUMER (warps 8-15) =================
        const int cw = w - 8;
        const int wm = cw & 1;
        const int wn = cw >> 1;
        const int rowA = wm * 32 + (lane & 15);
        const int rowB = wn * 32 + (lane & 15);
        const uint32_t kbl = (uint32_t)(lane >> 4) * 16;

        int buf = 0, ph = 0;      // consumer cursor
#pragma unroll 1
        for (int ci = 0; ci < NC; ci++) {
            MBARRIER_WAIT_PARITY(sb + SOFF_BAR + buf * 16, ph);      // full[buf]
            uint32_t base = tile0 + buf * BUF_SZ;
#pragma unroll
            for (int ks = 0; ks < 4; ks++) {
                uint32_t kb = (uint32_t)ks * 32 + kbl;
                uint32_t offA0 = SMEM_SWZ((uint32_t)(rowA * 128) + kb);
                uint32_t offA1 = SMEM_SWZ((uint32_t)((rowA + 16) * 128) + kb);
                uint32_t offB0 = SMEM_SWZ((uint32_t)(rowB * 128) + kb);
                uint32_t offB1 = SMEM_SWZ((uint32_t)((rowB + 16) * 128) + kb);
                uint32_t ah0[4], ah1[4], al0[4], al1[4];
                uint32_t bh0[4], bh1[4], bl0[4], bl1[4];
                LDSM_X4(ah0, base + offA0);
                LDSM_X4(ah1, base + offA1);
                LDSM_X4(al0, base + TILE_A_LO + offA0);
                LDSM_X4(al1, base + TILE_A_LO + offA1);
                LDSM_X4(bh0, base + TILE_B_HI + offB0);
                LDSM_X4(bh1, base + TILE_B_HI + offB1);
                LDSM_X4(bl0, base + TILE_B_LO + offB0);
                LDSM_X4(bl1, base + TILE_B_LO + offB1);
                // term-major order: same-acc reuse gap = 8 issues (> HMMA lat)
#pragma unroll
                for (int nt = 0; nt < 4; nt++) {
                    uint32_t* BH = (nt < 2) ? bh0 : bh1;
                    int p = nt & 1;
                    MMA16816(acc[0][nt], ah0, BH[p], BH[2 + p]);
                    MMA16816(acc[1][nt], ah1, BH[p], BH[2 + p]);
                }
#pragma unroll
                for (int nt = 0; nt < 4; nt++) {
                    uint32_t* BL = (nt < 2) ? bl0 : bl1;
                    int p = nt & 1;
                    MMA16816(acc[0][nt], ah0, BL[p], BL[2 + p]);
                    MMA16816(acc[1][nt], ah1, BL[p], BL[2 + p]);
                }
#pragma unroll
                for (int nt = 0; nt < 4; nt++) {
                    uint32_t* BH = (nt < 2) ? bh0 : bh1;
                    int p = nt & 1;
                    MMA16816(acc[0][nt], al0, BH[p], BH[2 + p]);
                    MMA16816(acc[1][nt], al1, BH[p], BH[2 + p]);
                }
            }
            MBARRIER_ARRIVE(sb + SOFF_BAR + buf * 16 + 8);           // empty[buf]
            if (++buf == STAGES) { buf = 0; ph ^= 1; }
        }
    }

    // ================= EPILOGUE (all 512 threads) =================
    if (t < 256) redp[t] = y2p;
    __syncthreads();
    float* lt = (float*)sm_t;   // stage-0 buffer free (last chunk used buf 2)
    if (w >= 8) {
        const int cw = w - 8;
        const int wm = cw & 1;
        const int wn = cw >> 1;
#pragma unroll
        for (int mt = 0; mt < 2; mt++) {
#pragma unroll
            for (int nt = 0; nt < 4; nt++) {
                int mrow = wm * 32 + mt * 16 + (lane >> 2);
                int col  = wn * 32 + nt * 8 + (lane & 3) * 2;
                lt[mrow * 128 + col]           = acc[mt][nt][0];
                lt[mrow * 128 + col + 1]       = acc[mt][nt][1];
                lt[(mrow + 8) * 128 + col]     = acc[mt][nt][2];
                lt[(mrow + 8) * 128 + col + 1] = acc[mt][nt][3];
            }
        }
    }
    if (t < 128) y2s[t] = redp[2 * t] + redp[2 * t + 1];
    __syncthreads();

    const int GB = gridDim.x;
#pragma unroll
    for (int it = 0; it < 4; it++) {
        int b = it * 16 + w;
        int nn = lane * 4;
        int n = n0 + nn;
        float x2b = (g_px[b * 4 + 0] + g_px[b * 4 + 1])
                  + (g_px[b * 4 + 2] + g_px[b * 4 + 3]);
        float sg = sigma[b];
        float iv = 1.0f / (sg * sg);
        float4 o = make_float4(0.f, 0.f, 0.f, 0.f);
        bool valid = (n < N);              // N % 4 == 0 -> whole float4 valid
        if (valid) {
            float4 dv = *(float4*)(lt + b * 128 + nn);
            o.x = -0.5f * fmaxf(x2b + y2s[nn]     - 2.0f * dv.x, 0.0f) * iv;
            o.y = -0.5f * fmaxf(x2b + y2s[nn + 1] - 2.0f * dv.y, 0.0f) * iv;
            o.z = -0.5f * fmaxf(x2b + y2s[nn + 2] - 2.0f * dv.z, 0.0f) * iv;
            o.w = -0.5f * fmaxf(x2b + y2s[nn + 3] - 2.0f * dv.w, 0.0f) * iv;
            *(float4*)(g_logits + (size_t)b * N + n) = o;
        }
        float mx = valid ? fmaxf(fmaxf(o.x, o.y), fmaxf(o.z, o.w)) : -3.4e38f;
#pragma unroll
        for (int q = 16; q > 0; q >>= 1)
            mx = fmaxf(mx, __shfl_xor_sync(0xffffffff, mx, q));
        float se = 0.f;
        if (valid)
            se = expf(o.x - mx) + expf(o.y - mx) + expf(o.z - mx) + expf(o.w - mx);
#pragma unroll
        for (int q = 16; q > 0; q >>= 1)
            se += __shfl_xor_sync(0xffffffff, se, q);
        if (lane == 0) {
            g_pm[(size_t)b * GB + blockIdx.x] = mx;
            g_ps[(size_t)b * GB + blockIdx.x] = se;
        }
    }
}

// ---------------------------------------------------------------------------
// K2: merge per-CTA softmax partials (GB per b) + build hot-tile worklist.
// ---------------------------------------------------------------------------
__global__ void k_stats_comb(int GB) {
    int b = blockIdx.x, t = threadIdx.x;
    __shared__ float red[256];
    const float* pm = g_pm + (size_t)b * GB;
    const float* ps = g_ps + (size_t)b * GB;
    float m = -3.4e38f;
    for (int i = t; i < GB; i += 256) m = fmaxf(m, pm[i]);
    red[t] = m;
    __syncthreads();
    for (int o = 128; o > 0; o >>= 1) {
        if (t < o) red[t] = fmaxf(red[t], red[t + o]);
        __syncthreads();
    }
    float M = red[0];
    __syncthreads();
    float s = 0.f;
    for (int i = t; i < GB; i += 256) s += ps[i] * expf(pm[i] - M);
    red[t] = s;
    __syncthreads();
    for (int o = 128; o > 0; o >>= 1) {
        if (t < o) red[t] += red[t + o];
        __syncthreads();
    }
    float S = red[0];
    if (t == 0) { g_m[b] = M; g_is[b] = 1.0f / S; }
    // worklist: tile hot iff exp(pm - M)/S * 128 > 1e-12
    float thr = M - 32.4849f + logf(S);
    for (int i = t; i < GB; i += 256) {
        if (pm[i] >= thr) {
            int p = atomicAdd(&g_wcnt, 1);
            g_wl[p] = (b << 9) | i;
        }
    }
}

// ---------------------------------------------------------------------------
// K3: worklist-driven sparse gather, D split across blockIdx.y halves.
// grid (OGRID, 2): half h covers dims [h*1536, (h+1)*1536).
// ---------------------------------------------------------------------------
#define DREG (DFIX / 512)     // 6 per half
#define OGRID 2048

__global__ void __launch_bounds__(256)
k_out(const float* __restrict__ Y, float* __restrict__ out, int N, int D) {
    int t = threadIdx.x;
    int h = blockIdx.y;
    int dbase = h * (D / 2) + t;
    __shared__ int   lidx[128];
    __shared__ float lw[128];
    __shared__ int   cnt;

    int total = g_wcnt;
#pragma unroll 1
    for (int idx = blockIdx.x; idx < total; idx += OGRID) {
        int e  = g_wl[idx];
        int b  = e >> 9;
        int ti = e & 511;
        float M  = g_m[b];
        float IS = g_is[b];
        if (t == 0) cnt = 0;
        __syncthreads();
        if (t < 128) {
            int n = ti * 128 + t;
            if (n < N) {
                float wv = expf(g_logits[(size_t)b * N + n] - M) * IS;
                if (wv > 1e-12f) {
                    int p = atomicAdd(&cnt, 1);
                    lidx[p] = n;
                    lw[p] = wv;
                }
            }
        }
        __syncthreads();
        int c = cnt;
        if (c > 0) {
            float racc[DREG];
#pragma unroll
            for (int i = 0; i < DREG; i++) racc[i] = 0.f;
            for (int e2 = 0; e2 < c; e2++) {
                int n = lidx[e2];
                float wv = lw[e2];
                const float* yr = Y + (size_t)n * D + dbase;
#pragma unroll
                for (int i = 0; i < DREG; i++)
                    racc[i] = fmaf(wv, yr[i * 256], racc[i]);
            }
#pragma unroll
            for (int i = 0; i < DREG; i++)
                atomicAdd(&out[(size_t)b * D + dbase + i * 256], racc[i]);
        }
        __syncthreads();   // lidx/lw/cnt reuse safety for next entry
    }
}

// ---------------------------------------------------------------------------
extern "C" void kernel_launch(void* const* d_in, const int* in_sizes, int n_in,
                              void* d_out, int out_size) {
    const float* x     = (const float*)d_in[0];
    const float* sigma = (const float*)d_in[1];
    const float* Y     = (const float*)d_in[2];
    float* out = (float*)d_out;

    int B = in_sizes[1];             // 64
    int D = in_sizes[0] / B;         // 3072
    int N = in_sizes[2] / D;         // 50000
    int GB = (N + NT - 1) / NT;      // 391

    cudaFuncSetAttribute(k_gemm, cudaFuncAttributeMaxDynamicSharedMemorySize, SMEM_TOTAL);

    dim3 gp(B, 4);
    k_prep<<<gp, 256>>>(x, out, D);
    k_gemm<<<GB, 512, SMEM_TOTAL>>>(Y, sigma, N, D);
    k_stats_comb<<<B, 256>>>(GB);
    dim3 go(OGRID, 2);
    k_out<<<go, 256>>>(Y, out, N, D);
}